// round 3
// baseline (speedup 1.0000x reference)
#include <cuda_runtime.h>
#include <cuda_bf16.h>

#define N_NODES   50000
#define NUM_FEAT  64
#define HIDDEN    512
#define N_EDGES   800000
#define BN_EPS    1e-5f

// ---------------- scratch (static device globals; no allocation) ----------------
__device__ float g_agg[(size_t)N_NODES * NUM_FEAT];     // 12.8 MB  (x + neighbor sum)
__device__ float g_h1 [(size_t)N_NODES * HIDDEN];       // 102.4 MB
__device__ float g_h2 [(size_t)N_NODES * HIDDEN];       // 102.4 MB
__device__ float g_sum  [HIDDEN];
__device__ float g_sumsq[HIDDEN];
__device__ float g_scale[HIDDEN];
__device__ float g_shift[HIDDEN];
__device__ int   g_idx64;                               // 1 if edge_index is int64

// ---------------- detect edge_index dtype (int64 vs int32) ----------------
// Genuine int64 indices are all in [0, N_NODES). If the buffer actually holds
// int32s, interpreting as int64 packs two indices per word -> huge values.
__global__ void detect_kernel(const long long* __restrict__ ei) {
    int is64 = 1;
    for (int i = 0; i < 64; i++) {
        long long v = ei[i];
        if (v < 0 || v >= N_NODES) { is64 = 0; break; }
    }
    g_idx64 = is64;
}

// ---------------- init: agg = x, zero BN accumulators ----------------
__global__ void init_kernel(const float* __restrict__ x) {
    int i = blockIdx.x * blockDim.x + threadIdx.x;              // 800000 threads
    ((float4*)g_agg)[i] = ((const float4*)x)[i];                // exact cover: 50000*64/4
    if (i < HIDDEN) { g_sum[i] = 0.f; g_sumsq[i] = 0.f; }
}

// ---------------- edge aggregation: agg[dst] += x[src] ----------------
// one thread per (edge, 4-feature chunk): 800k * 16 threads, 4 atomics each
__global__ void agg_kernel(const float* __restrict__ x, const void* __restrict__ ei_raw) {
    int g = blockIdx.x * blockDim.x + threadIdx.x;              // < 12.8M, fits int
    int e  = g >> 4;
    int c  = (g & 15) << 2;
    if (e >= N_EDGES) return;
    int src, dst;
    if (g_idx64) {
        const long long* ei = (const long long*)ei_raw;
        src = (int)ei[e];
        dst = (int)ei[N_EDGES + e];
    } else {
        const int* ei = (const int*)ei_raw;
        src = ei[e];
        dst = ei[N_EDGES + e];
    }
    if ((unsigned)src >= N_NODES || (unsigned)dst >= N_NODES) return;  // never crash
    float4 v = *(const float4*)&x[src * NUM_FEAT + c];
    float* d = &g_agg[dst * NUM_FEAT + c];
    atomicAdd(d + 0, v.x);
    atomicAdd(d + 1, v.y);
    atomicAdd(d + 2, v.z);
    atomicAdd(d + 3, v.w);
}

// ---------------- SGEMM: C[M,N] = act(A[M,K] @ B[K,N] + bias) ----------------
// MODE 0: A=g_agg (K=64),  C=g_h1, ReLU
// MODE 1: A=g_h1  (K=512), C=g_h2, no ReLU
// 128x128 block tile, BK=8, 256 threads, 8x8 microtile (split 4+4 with stride 64)
template<int MODE>
__global__ __launch_bounds__(256, 2)
void gemm_kernel(const float* __restrict__ B, const float* __restrict__ bias) {
    constexpr int M = N_NODES;
    constexpr int N = HIDDEN;
    constexpr int K = (MODE == 0) ? NUM_FEAT : HIDDEN;
    constexpr int RELU = (MODE == 0) ? 1 : 0;
    const float* __restrict__ A = (MODE == 0) ? g_agg : g_h1;
    float* __restrict__ C       = (MODE == 0) ? g_h1  : g_h2;

    __shared__ float As[8][128];
    __shared__ float Bs[8][128];

    const int tid = threadIdx.x;
    const int bm  = blockIdx.x * 128;
    const int bn  = blockIdx.y * 128;
    const int ty  = tid >> 4;          // 0..15
    const int tx  = tid & 15;          // 0..15

    // global load indices
    const int arow = tid >> 1;         // 0..127
    const int acol = (tid & 1) << 2;   // 0 or 4
    const int brow = tid >> 5;         // 0..7
    const int bcol = (tid & 31) << 2;  // 0..124

    const bool aval = (bm + arow) < M;
    const float* Aptr = A + (long long)(bm + arow) * K + acol;
    const float* Bptr = B + (long long)brow * N + bn + bcol;

    float acc[8][8];
    #pragma unroll
    for (int i = 0; i < 8; i++)
        #pragma unroll
        for (int j = 0; j < 8; j++) acc[i][j] = 0.f;

    #pragma unroll 1
    for (int k0 = 0; k0 < K; k0 += 8) {
        float4 a = aval ? *(const float4*)(Aptr + k0) : make_float4(0.f, 0.f, 0.f, 0.f);
        float4 b = *(const float4*)(Bptr + (long long)k0 * N);
        __syncthreads();
        As[acol + 0][arow] = a.x;
        As[acol + 1][arow] = a.y;
        As[acol + 2][arow] = a.z;
        As[acol + 3][arow] = a.w;
        *(float4*)&Bs[brow][bcol] = b;
        __syncthreads();

        #pragma unroll
        for (int k = 0; k < 8; k++) {
            float4 a0 = *(float4*)&As[k][ty * 4];
            float4 a1 = *(float4*)&As[k][64 + ty * 4];
            float4 b0 = *(float4*)&Bs[k][tx * 4];
            float4 b1 = *(float4*)&Bs[k][64 + tx * 4];
            float am[8] = {a0.x, a0.y, a0.z, a0.w, a1.x, a1.y, a1.z, a1.w};
            float bv[8] = {b0.x, b0.y, b0.z, b0.w, b1.x, b1.y, b1.z, b1.w};
            #pragma unroll
            for (int i = 0; i < 8; i++)
                #pragma unroll
                for (int j = 0; j < 8; j++)
                    acc[i][j] = fmaf(am[i], bv[j], acc[i][j]);
        }
    }

    // epilogue: bias (+ReLU), vectorized stores
    #pragma unroll
    for (int i = 0; i < 8; i++) {
        int row = bm + ((i < 4) ? (ty * 4 + i) : (64 + ty * 4 + i - 4));
        if (row >= M) continue;
        #pragma unroll
        for (int jq = 0; jq < 2; jq++) {
            int col = bn + (jq ? (64 + tx * 4) : (tx * 4));
            float4 r;
            r.x = acc[i][jq * 4 + 0] + bias[col + 0];
            r.y = acc[i][jq * 4 + 1] + bias[col + 1];
            r.z = acc[i][jq * 4 + 2] + bias[col + 2];
            r.w = acc[i][jq * 4 + 3] + bias[col + 3];
            if (RELU) {
                r.x = fmaxf(r.x, 0.f); r.y = fmaxf(r.y, 0.f);
                r.z = fmaxf(r.z, 0.f); r.w = fmaxf(r.w, 0.f);
            }
            *(float4*)&C[(long long)row * N + col] = r;
        }
    }
}

// ---------------- BN statistics: per-column sum / sumsq ----------------
#define BN_ROWS_PER 500
__global__ void bn_stats_kernel() {
    int col  = blockIdx.x * 128 + threadIdx.x;      // gridDim.x = 4, blockDim = 128
    int rbeg = blockIdx.y * BN_ROWS_PER;            // gridDim.y = 100
    float s = 0.f, q = 0.f;
    const float* p = &g_h2[(long long)rbeg * HIDDEN + col];
    #pragma unroll 4
    for (int r = 0; r < BN_ROWS_PER; r++) {
        float v = p[(long long)r * HIDDEN];
        s += v;
        q = fmaf(v, v, q);
    }
    atomicAdd(&g_sum[col], s);
    atomicAdd(&g_sumsq[col], q);
}

__global__ void bn_finalize_kernel(const float* __restrict__ gamma,
                                   const float* __restrict__ beta) {
    int c = threadIdx.x;                            // 512 threads
    float inv_n = 1.0f / (float)N_NODES;
    float mean = g_sum[c] * inv_n;
    float var  = g_sumsq[c] * inv_n - mean * mean;
    float sc   = gamma[c] * rsqrtf(var + BN_EPS);
    g_scale[c] = sc;
    g_shift[c] = beta[c] - mean * sc;
}

// ---------------- fused BN-apply + ReLU + classifier ----------------
// one warp per row; 8 rows per block
__global__ __launch_bounds__(256)
void cls_kernel(const float* __restrict__ Wc, const float* __restrict__ bc,
                float* __restrict__ out) {
    __shared__ float s_scale[HIDDEN], s_shift[HIDDEN], s_w0[HIDDEN], s_w1[HIDDEN];
    int tid = threadIdx.x;
    for (int c = tid; c < HIDDEN; c += 256) {
        s_scale[c] = g_scale[c];
        s_shift[c] = g_shift[c];
        s_w0[c] = Wc[c * 2 + 0];
        s_w1[c] = Wc[c * 2 + 1];
    }
    __syncthreads();

    int warp = tid >> 5, lane = tid & 31;
    int row = blockIdx.x * 8 + warp;                // grid = 6250, exact
    const float4* h = (const float4*)&g_h2[(long long)row * HIDDEN];
    float a0 = 0.f, a1 = 0.f;
    #pragma unroll
    for (int it = 0; it < 4; it++) {
        int c4 = it * 32 + lane;
        float4 v = h[c4];
        int c = c4 * 4;
        float t;
        t = fmaxf(fmaf(v.x, s_scale[c + 0], s_shift[c + 0]), 0.f);
        a0 = fmaf(t, s_w0[c + 0], a0); a1 = fmaf(t, s_w1[c + 0], a1);
        t = fmaxf(fmaf(v.y, s_scale[c + 1], s_shift[c + 1]), 0.f);
        a0 = fmaf(t, s_w0[c + 1], a0); a1 = fmaf(t, s_w1[c + 1], a1);
        t = fmaxf(fmaf(v.z, s_scale[c + 2], s_shift[c + 2]), 0.f);
        a0 = fmaf(t, s_w0[c + 2], a0); a1 = fmaf(t, s_w1[c + 2], a1);
        t = fmaxf(fmaf(v.w, s_scale[c + 3], s_shift[c + 3]), 0.f);
        a0 = fmaf(t, s_w0[c + 3], a0); a1 = fmaf(t, s_w1[c + 3], a1);
    }
    #pragma unroll
    for (int o = 16; o > 0; o >>= 1) {
        a0 += __shfl_down_sync(0xFFFFFFFFu, a0, o);
        a1 += __shfl_down_sync(0xFFFFFFFFu, a1, o);
    }
    if (lane == 0) {
        out[row * 2 + 0] = a0 + bc[0];
        out[row * 2 + 1] = a1 + bc[1];
    }
}

// ---------------- launch ----------------
extern "C" void kernel_launch(void* const* d_in, const int* in_sizes, int n_in,
                              void* d_out, int out_size) {
    const float* x     = (const float*)d_in[0];
    const void*  ei    = d_in[1];
    const float* W1    = (const float*)d_in[2];
    const float* b1    = (const float*)d_in[3];
    const float* W2    = (const float*)d_in[4];
    const float* b2    = (const float*)d_in[5];
    const float* gamma = (const float*)d_in[6];
    const float* beta  = (const float*)d_in[7];
    const float* Wc    = (const float*)d_in[8];
    const float* bc    = (const float*)d_in[9];
    float*       out   = (float*)d_out;

    // 0) detect edge_index dtype (int64 vs int32)
    detect_kernel<<<1, 1>>>((const long long*)ei);

    // 1) agg = x ; zero BN accumulators
    init_kernel<<<(N_NODES * NUM_FEAT / 4) / 256, 256>>>(x);

    // 2) agg[dst] += x[src]
    agg_kernel<<<(N_EDGES * 16) / 256, 256>>>(x, ei);

    // 3) h1 = relu(agg @ W1 + b1)     [50000,64]x[64,512]
    dim3 g1((N_NODES + 127) / 128, HIDDEN / 128);
    gemm_kernel<0><<<g1, 256>>>(W1, b1);

    // 4) h2 = h1 @ W2 + b2            [50000,512]x[512,512]
    gemm_kernel<1><<<g1, 256>>>(W2, b2);

    // 5) BN batch statistics
    dim3 gs(HIDDEN / 128, N_NODES / BN_ROWS_PER);
    bn_stats_kernel<<<gs, 128>>>();
    bn_finalize_kernel<<<1, HIDDEN>>>(gamma, beta);

    // 6) out = relu(BN(h2)) @ Wc + bc
    cls_kernel<<<N_NODES / 8, 256>>>(Wc, bc, out);
}

// round 5
// speedup vs baseline: 1.7242x; 1.7242x over previous
#include <cuda_runtime.h>
#include <cuda_bf16.h>
#include <cstdint>

#define N_NODES   50000
#define NUM_FEAT  64
#define HIDDEN    512
#define N_EDGES   800000
#define BN_EPS    1e-5f

// ================= helpers =================
__device__ __forceinline__ uint32_t smem_u32(const void* p) {
    uint32_t a;
    asm("{ .reg .u64 t; cvta.to.shared.u64 t, %1; cvt.u32.u64 %0, t; }" : "=r"(a) : "l"(p));
    return a;
}
__device__ __forceinline__ uint32_t f2tf32(float x) {
    uint32_t u;
    asm("cvt.rna.tf32.f32 %0, %1;" : "=r"(u) : "f"(x));
    return u;
}
__device__ __forceinline__ void mma_tf32(float* d, const uint32_t* a, const uint32_t* b) {
    asm volatile("mma.sync.aligned.m16n8k8.row.col.f32.tf32.tf32.f32 "
        "{%0,%1,%2,%3}, {%4,%5,%6,%7}, {%8,%9}, {%0,%1,%2,%3};"
        : "+f"(d[0]), "+f"(d[1]), "+f"(d[2]), "+f"(d[3])
        : "r"(a[0]), "r"(a[1]), "r"(a[2]), "r"(a[3]), "r"(b[0]), "r"(b[1]));
}
__device__ __forceinline__ void cp_async16(uint32_t dst, const void* src, int src_bytes) {
    asm volatile("cp.async.cg.shared.global [%0], [%1], 16, %2;"
                 :: "r"(dst), "l"(src), "r"(src_bytes) : "memory");
}
#define CP_COMMIT() asm volatile("cp.async.commit_group;" ::: "memory")

// ================= scratch (static device globals) =================
__device__ float g_agg[(size_t)N_NODES * NUM_FEAT];     // 12.8 MB
__device__ float g_h1 [(size_t)N_NODES * HIDDEN];       // 102.4 MB
__device__ float g_h2 [(size_t)N_NODES * HIDDEN];       // 102.4 MB
__device__ float g_w1t[(size_t)HIDDEN * NUM_FEAT];      // W1^T [512,64]
__device__ float g_w2t[(size_t)HIDDEN * HIDDEN];        // W2^T [512,512]
__device__ float g_sum  [HIDDEN];
__device__ float g_sumsq[HIDDEN];
__device__ float g_scale[HIDDEN];
__device__ float g_shift[HIDDEN];
__device__ int   g_idx64;

// ================= dtype detect (int64 vs int32 edge_index) =================
__global__ void detect_kernel(const long long* __restrict__ ei) {
    int is64 = 1;
    for (int i = 0; i < 64; i++) {
        long long v = ei[i];
        if (v < 0 || v >= N_NODES) { is64 = 0; break; }
    }
    g_idx64 = is64;
}

// ================= init: agg = x, zero BN accumulators =================
__global__ void init_kernel(const float* __restrict__ x) {
    int i = blockIdx.x * blockDim.x + threadIdx.x;
    ((float4*)g_agg)[i] = ((const float4*)x)[i];
    if (i < HIDDEN) { g_sum[i] = 0.f; g_sumsq[i] = 0.f; }
}

// ================= edge aggregation: agg[dst] += x[src] =================
__global__ void agg_kernel(const float* __restrict__ x, const void* __restrict__ ei_raw) {
    int g = blockIdx.x * blockDim.x + threadIdx.x;
    int e = g >> 4;
    int c = (g & 15) << 2;
    if (e >= N_EDGES) return;
    int src, dst;
    if (g_idx64) {
        const long long* ei = (const long long*)ei_raw;
        src = (int)ei[e];
        dst = (int)ei[N_EDGES + e];
    } else {
        const int* ei = (const int*)ei_raw;
        src = ei[e];
        dst = ei[N_EDGES + e];
    }
    if ((unsigned)src >= N_NODES || (unsigned)dst >= N_NODES) return;
    float4 v = *(const float4*)&x[src * NUM_FEAT + c];
    float* d = &g_agg[dst * NUM_FEAT + c];
    atomicAdd(d + 0, v.x);
    atomicAdd(d + 1, v.y);
    atomicAdd(d + 2, v.z);
    atomicAdd(d + 3, v.w);
}

// ================= weight transpose: W[KR,512] -> WT[512,KR] =================
template<int KR>
__global__ void tr_kernel(const float* __restrict__ W) {
    __shared__ float t[32][33];
    float* dst = (KR == NUM_FEAT) ? g_w1t : g_w2t;
    int c0 = blockIdx.x * 32;
    int r0 = blockIdx.y * 32;
    t[threadIdx.y][threadIdx.x] = W[(r0 + threadIdx.y) * HIDDEN + c0 + threadIdx.x];
    __syncthreads();
    dst[(c0 + threadIdx.y) * KR + r0 + threadIdx.x] = t[threadIdx.x][threadIdx.y];
}

// ================= tf32 mma.sync GEMM =================
// MODE 0: g_h1 = relu(g_agg[50000,64] @ W1 + b1)
// MODE 1: g_h2 =      g_h1 [50000,512] @ W2 + b2
// Block 128x128, BK=16, 8 warps (4 M x 2 N), warp tile 32x64.
// cp.async double-buffered; tf32 conversion (RNA) at fragment load.
template<int MODE>
__global__ __launch_bounds__(256)
void gemm_mma_kernel(const float* __restrict__ bias) {
    constexpr int M = N_NODES;
    constexpr int N = HIDDEN;
    constexpr int K = (MODE == 0) ? NUM_FEAT : HIDDEN;
    constexpr int S = K / 16;
    constexpr int RELU = (MODE == 0) ? 1 : 0;
    const float* __restrict__ A  = (MODE == 0) ? g_agg : g_h1;
    const float* __restrict__ WT = (MODE == 0) ? g_w1t : g_w2t;
    float* __restrict__ C        = (MODE == 0) ? g_h1  : g_h2;

    __shared__ float As[2][128][20];   // padded: conflict-free fragment loads
    __shared__ float Bs[2][128][20];

    const int tid  = threadIdx.x;
    const int lane = tid & 31;
    const int wid  = tid >> 5;
    const int wm   = wid & 3;          // 0..3  (M)
    const int wn   = wid >> 2;         // 0..1  (N)
    const int m0   = blockIdx.x * 128;
    const int n0   = blockIdx.y * 128;

    auto issue = [&](int s) {
        const int buf = s & 1;
        const int k0  = s * 16;
        #pragma unroll
        for (int i = 0; i < 2; i++) {
            int idx = tid + i * 256;                 // 0..511
            int r = idx >> 2, q = (idx & 3) * 4;
            int row = m0 + r;
            bool v = row < M;
            int rc = v ? row : (M - 1);
            cp_async16(smem_u32(&As[buf][r][q]), &A[(size_t)rc * K + k0 + q], v ? 16 : 0);
        }
        #pragma unroll
        for (int i = 0; i < 2; i++) {
            int idx = tid + i * 256;
            int r = idx >> 2, q = (idx & 3) * 4;
            cp_async16(smem_u32(&Bs[buf][r][q]), &WT[(size_t)(n0 + r) * K + k0 + q], 16);
        }
        CP_COMMIT();
    };

    float acc[2][8][4];
    #pragma unroll
    for (int mi = 0; mi < 2; mi++)
        #pragma unroll
        for (int ni = 0; ni < 8; ni++)
            #pragma unroll
            for (int j = 0; j < 4; j++) acc[mi][ni][j] = 0.f;

    issue(0);
    if (S > 1) issue(1);

    #pragma unroll 1
    for (int s = 0; s < S; s++) {
        if (s + 1 < S) asm volatile("cp.async.wait_group 1;" ::: "memory");
        else           asm volatile("cp.async.wait_group 0;" ::: "memory");
        __syncthreads();
        const int buf = s & 1;

        #pragma unroll
        for (int k8 = 0; k8 < 2; k8++) {
            const int kc = k8 * 8 + (lane & 3);
            uint32_t a[2][4];
            #pragma unroll
            for (int mi = 0; mi < 2; mi++) {
                int r = wm * 32 + mi * 16 + (lane >> 2);
                a[mi][0] = f2tf32(As[buf][r][kc]);
                a[mi][1] = f2tf32(As[buf][r + 8][kc]);
                a[mi][2] = f2tf32(As[buf][r][kc + 4]);
                a[mi][3] = f2tf32(As[buf][r + 8][kc + 4]);
            }
            uint32_t b[8][2];
            #pragma unroll
            for (int ni = 0; ni < 8; ni++) {
                int n = wn * 64 + ni * 8 + (lane >> 2);
                b[ni][0] = f2tf32(Bs[buf][n][kc]);
                b[ni][1] = f2tf32(Bs[buf][n][kc + 4]);
            }
            #pragma unroll
            for (int mi = 0; mi < 2; mi++)
                #pragma unroll
                for (int ni = 0; ni < 8; ni++)
                    mma_tf32(acc[mi][ni], a[mi], b[ni]);
        }
        __syncthreads();
        if (s + 2 < S) issue(s + 2);
    }

    // epilogue: bias (+ReLU)
    #pragma unroll
    for (int mi = 0; mi < 2; mi++) {
        const int r0 = m0 + wm * 32 + mi * 16 + (lane >> 2);
        #pragma unroll
        for (int ni = 0; ni < 8; ni++) {
            const int col = n0 + wn * 64 + ni * 8 + (lane & 3) * 2;
            const float bx = __ldg(&bias[col]);
            const float by = __ldg(&bias[col + 1]);
            float2 v;
            if (r0 < M) {
                v.x = acc[mi][ni][0] + bx;
                v.y = acc[mi][ni][1] + by;
                if (RELU) { v.x = fmaxf(v.x, 0.f); v.y = fmaxf(v.y, 0.f); }
                *(float2*)&C[(size_t)r0 * N + col] = v;
            }
            if (r0 + 8 < M) {
                v.x = acc[mi][ni][2] + bx;
                v.y = acc[mi][ni][3] + by;
                if (RELU) { v.x = fmaxf(v.x, 0.f); v.y = fmaxf(v.y, 0.f); }
                *(float2*)&C[(size_t)(r0 + 8) * N + col] = v;
            }
        }
    }
}

// ================= BN statistics =================
#define BN_ROWS_PER 500
__global__ void bn_stats_kernel() {
    int col  = blockIdx.x * 128 + threadIdx.x;
    int rbeg = blockIdx.y * BN_ROWS_PER;
    float s = 0.f, q = 0.f;
    const float* p = &g_h2[(long long)rbeg * HIDDEN + col];
    #pragma unroll 4
    for (int r = 0; r < BN_ROWS_PER; r++) {
        float v = p[(long long)r * HIDDEN];
        s += v;
        q = fmaf(v, v, q);
    }
    atomicAdd(&g_sum[col], s);
    atomicAdd(&g_sumsq[col], q);
}

__global__ void bn_finalize_kernel(const float* __restrict__ gamma,
                                   const float* __restrict__ beta) {
    int c = threadIdx.x;
    float inv_n = 1.0f / (float)N_NODES;
    float mean = g_sum[c] * inv_n;
    float var  = g_sumsq[c] * inv_n - mean * mean;
    float sc   = gamma[c] * rsqrtf(var + BN_EPS);
    g_scale[c] = sc;
    g_shift[c] = beta[c] - mean * sc;
}

// ================= fused BN-apply + ReLU + classifier =================
__global__ __launch_bounds__(256)
void cls_kernel(const float* __restrict__ Wc, const float* __restrict__ bc,
                float* __restrict__ out) {
    __shared__ float s_scale[HIDDEN], s_shift[HIDDEN], s_w0[HIDDEN], s_w1[HIDDEN];
    int tid = threadIdx.x;
    for (int c = tid; c < HIDDEN; c += 256) {
        s_scale[c] = g_scale[c];
        s_shift[c] = g_shift[c];
        s_w0[c] = Wc[c * 2 + 0];
        s_w1[c] = Wc[c * 2 + 1];
    }
    __syncthreads();

    int warp = tid >> 5, lane = tid & 31;
    int row = blockIdx.x * 8 + warp;
    const float4* h = (const float4*)&g_h2[(long long)row * HIDDEN];
    float a0 = 0.f, a1 = 0.f;
    #pragma unroll
    for (int it = 0; it < 4; it++) {
        int c4 = it * 32 + lane;
        float4 v = h[c4];
        int c = c4 * 4;
        float t;
        t = fmaxf(fmaf(v.x, s_scale[c + 0], s_shift[c + 0]), 0.f);
        a0 = fmaf(t, s_w0[c + 0], a0); a1 = fmaf(t, s_w1[c + 0], a1);
        t = fmaxf(fmaf(v.y, s_scale[c + 1], s_shift[c + 1]), 0.f);
        a0 = fmaf(t, s_w0[c + 1], a0); a1 = fmaf(t, s_w1[c + 1], a1);
        t = fmaxf(fmaf(v.z, s_scale[c + 2], s_shift[c + 2]), 0.f);
        a0 = fmaf(t, s_w0[c + 2], a0); a1 = fmaf(t, s_w1[c + 2], a1);
        t = fmaxf(fmaf(v.w, s_scale[c + 3], s_shift[c + 3]), 0.f);
        a0 = fmaf(t, s_w0[c + 3], a0); a1 = fmaf(t, s_w1[c + 3], a1);
    }
    #pragma unroll
    for (int o = 16; o > 0; o >>= 1) {
        a0 += __shfl_down_sync(0xFFFFFFFFu, a0, o);
        a1 += __shfl_down_sync(0xFFFFFFFFu, a1, o);
    }
    if (lane == 0) {
        out[row * 2 + 0] = a0 + bc[0];
        out[row * 2 + 1] = a1 + bc[1];
    }
}

// ================= launch =================
extern "C" void kernel_launch(void* const* d_in, const int* in_sizes, int n_in,
                              void* d_out, int out_size) {
    const float* x     = (const float*)d_in[0];
    const void*  ei    = d_in[1];
    const float* W1    = (const float*)d_in[2];
    const float* b1    = (const float*)d_in[3];
    const float* W2    = (const float*)d_in[4];
    const float* b2    = (const float*)d_in[5];
    const float* gamma = (const float*)d_in[6];
    const float* beta  = (const float*)d_in[7];
    const float* Wc    = (const float*)d_in[8];
    const float* bc    = (const float*)d_in[9];
    float*       out   = (float*)d_out;

    // 0) detect edge_index dtype
    detect_kernel<<<1, 1>>>((const long long*)ei);

    // 1) agg = x ; zero BN accumulators
    init_kernel<<<(N_NODES * NUM_FEAT / 4) / 256, 256>>>(x);

    // 2) agg[dst] += x[src]
    agg_kernel<<<(N_EDGES * 16) / 256, 256>>>(x, ei);

    // 2b) weight transposes
    tr_kernel<NUM_FEAT><<<dim3(HIDDEN / 32, NUM_FEAT / 32), dim3(32, 32)>>>(W1);
    tr_kernel<HIDDEN>  <<<dim3(HIDDEN / 32, HIDDEN / 32),   dim3(32, 32)>>>(W2);

    // 3) h1 = relu(agg @ W1 + b1)   tf32 mma.sync
    dim3 gg((N_NODES + 127) / 128, HIDDEN / 128);
    gemm_mma_kernel<0><<<gg, 256>>>(b1);

    // 4) h2 = h1 @ W2 + b2          tf32 mma.sync
    gemm_mma_kernel<1><<<gg, 256>>>(b2);

    // 5) BN batch statistics
    dim3 gs(HIDDEN / 128, N_NODES / BN_ROWS_PER);
    bn_stats_kernel<<<gs, 128>>>();
    bn_finalize_kernel<<<1, HIDDEN>>>(gamma, beta);

    // 6) out = relu(BN(h2)) @ Wc + bc
    cls_kernel<<<N_NODES / 8, 256>>>(Wc, bc, out);
}

// round 6
// speedup vs baseline: 2.3046x; 1.3366x over previous
#include <cuda_runtime.h>
#include <cuda_bf16.h>
#include <cstdint>

#define N_NODES   50000
#define NUM_FEAT  64
#define HIDDEN    512
#define N_EDGES   800000
#define BN_EPS    1e-5f

// ================= helpers =================
__device__ __forceinline__ uint32_t smem_u32(const void* p) {
    uint32_t a;
    asm("{ .reg .u64 t; cvta.to.shared.u64 t, %1; cvt.u32.u64 %0, t; }" : "=r"(a) : "l"(p));
    return a;
}
__device__ __forceinline__ uint32_t f2tf32(float x) {
    uint32_t u;
    asm("cvt.rna.tf32.f32 %0, %1;" : "=r"(u) : "f"(x));
    return u;
}
__device__ __forceinline__ void mma_tf32(float* d, const uint32_t* a, const uint32_t* b) {
    asm volatile("mma.sync.aligned.m16n8k8.row.col.f32.tf32.tf32.f32 "
        "{%0,%1,%2,%3}, {%4,%5,%6,%7}, {%8,%9}, {%0,%1,%2,%3};"
        : "+f"(d[0]), "+f"(d[1]), "+f"(d[2]), "+f"(d[3])
        : "r"(a[0]), "r"(a[1]), "r"(a[2]), "r"(a[3]), "r"(b[0]), "r"(b[1]));
}
__device__ __forceinline__ void cp_async16(uint32_t dst, const void* src, int src_bytes) {
    asm volatile("cp.async.cg.shared.global [%0], [%1], 16, %2;"
                 :: "r"(dst), "l"(src), "r"(src_bytes) : "memory");
}
#define CP_COMMIT() asm volatile("cp.async.commit_group;" ::: "memory")

// ================= scratch (static device globals) =================
__device__ float g_agg[(size_t)N_NODES * NUM_FEAT];     // 12.8 MB
__device__ float g_h1 [(size_t)N_NODES * HIDDEN];       // 102.4 MB (tf32-rounded)
__device__ float g_h2 [(size_t)N_NODES * HIDDEN];       // 102.4 MB
__device__ float g_w1t[(size_t)HIDDEN * NUM_FEAT];      // W1^T (tf32-rounded)
__device__ float g_w2t[(size_t)HIDDEN * HIDDEN];        // W2^T (tf32-rounded)
__device__ float g_sum  [HIDDEN];
__device__ float g_sumsq[HIDDEN];
__device__ float g_scale[HIDDEN];
__device__ float g_shift[HIDDEN];
__device__ int   g_idx64;

// ================= dtype detect (int64 vs int32 edge_index) =================
__global__ void detect_kernel(const long long* __restrict__ ei) {
    int is64 = 1;
    for (int i = 0; i < 64; i++) {
        long long v = ei[i];
        if (v < 0 || v >= N_NODES) { is64 = 0; break; }
    }
    g_idx64 = is64;
}

// ================= init: agg = x, zero BN accumulators =================
__global__ void init_kernel(const float* __restrict__ x) {
    int i = blockIdx.x * blockDim.x + threadIdx.x;
    ((float4*)g_agg)[i] = ((const float4*)x)[i];
    if (i < HIDDEN) { g_sum[i] = 0.f; g_sumsq[i] = 0.f; }
}

// ================= edge aggregation: agg[dst] += x[src] =================
__global__ void agg_kernel(const float* __restrict__ x, const void* __restrict__ ei_raw) {
    int g = blockIdx.x * blockDim.x + threadIdx.x;
    int e = g >> 4;
    int c = (g & 15) << 2;
    if (e >= N_EDGES) return;
    int src, dst;
    if (g_idx64) {
        const long long* ei = (const long long*)ei_raw;
        src = (int)ei[e];
        dst = (int)ei[N_EDGES + e];
    } else {
        const int* ei = (const int*)ei_raw;
        src = ei[e];
        dst = ei[N_EDGES + e];
    }
    if ((unsigned)src >= N_NODES || (unsigned)dst >= N_NODES) return;
    float4 v = *(const float4*)&x[src * NUM_FEAT + c];
    float* d = &g_agg[dst * NUM_FEAT + c];
    asm volatile("red.global.add.v4.f32 [%0], {%1, %2, %3, %4};"
                 :: "l"(d), "f"(v.x), "f"(v.y), "f"(v.z), "f"(v.w) : "memory");
}

// ================= weight transpose + tf32 round: W[KR,512] -> WT[512,KR] =================
template<int KR>
__global__ void tr_kernel(const float* __restrict__ W) {
    __shared__ float t[32][33];
    float* dst = (KR == NUM_FEAT) ? g_w1t : g_w2t;
    int c0 = blockIdx.x * 32;
    int r0 = blockIdx.y * 32;
    t[threadIdx.y][threadIdx.x] = W[(r0 + threadIdx.y) * HIDDEN + c0 + threadIdx.x];
    __syncthreads();
    dst[(c0 + threadIdx.y) * KR + r0 + threadIdx.x] =
        __uint_as_float(f2tf32(t[threadIdx.x][threadIdx.y]));
}

// ================= tf32 mma.sync GEMM =================
// MODE 0: g_h1 = tf32round(relu(g_agg @ W1 + b1))   [A needs cvt; B pre-rounded]
// MODE 1: g_h2 = g_h1 @ W2 + b2                     [no cvt; fused BN column stats]
// Block 128x128, BK=16, 8 warps (4 M x 2 N), warp tile 32x64, cp.async 2-stage.
template<int MODE>
__global__ __launch_bounds__(256)
void gemm_mma_kernel(const float* __restrict__ bias) {
    constexpr int M = N_NODES;
    constexpr int N = HIDDEN;
    constexpr int K = (MODE == 0) ? NUM_FEAT : HIDDEN;
    constexpr int S = K / 16;
    const float* __restrict__ A  = (MODE == 0) ? g_agg : g_h1;
    const float* __restrict__ WT = (MODE == 0) ? g_w1t : g_w2t;
    float* __restrict__ C        = (MODE == 0) ? g_h1  : g_h2;

    __shared__ float As[2][128][20];
    __shared__ float Bs[2][128][20];

    const int tid  = threadIdx.x;
    const int lane = tid & 31;
    const int wid  = tid >> 5;
    const int wm   = wid & 3;
    const int wn   = wid >> 2;
    const int m0   = blockIdx.x * 128;
    const int n0   = blockIdx.y * 128;

    auto issue = [&](int s) {
        const int buf = s & 1;
        const int k0  = s * 16;
        #pragma unroll
        for (int i = 0; i < 2; i++) {
            int idx = tid + i * 256;
            int r = idx >> 2, q = (idx & 3) * 4;
            int row = m0 + r;
            bool v = row < M;
            int rc = v ? row : (M - 1);
            cp_async16(smem_u32(&As[buf][r][q]), &A[(size_t)rc * K + k0 + q], v ? 16 : 0);
        }
        #pragma unroll
        for (int i = 0; i < 2; i++) {
            int idx = tid + i * 256;
            int r = idx >> 2, q = (idx & 3) * 4;
            cp_async16(smem_u32(&Bs[buf][r][q]), &WT[(size_t)(n0 + r) * K + k0 + q], 16);
        }
        CP_COMMIT();
    };

    float acc[2][8][4];
    #pragma unroll
    for (int mi = 0; mi < 2; mi++)
        #pragma unroll
        for (int ni = 0; ni < 8; ni++)
            #pragma unroll
            for (int j = 0; j < 4; j++) acc[mi][ni][j] = 0.f;

    issue(0);
    if (S > 1) issue(1);

    #pragma unroll 1
    for (int s = 0; s < S; s++) {
        if (s + 1 < S) asm volatile("cp.async.wait_group 1;" ::: "memory");
        else           asm volatile("cp.async.wait_group 0;" ::: "memory");
        __syncthreads();
        const int buf = s & 1;

        #pragma unroll
        for (int k8 = 0; k8 < 2; k8++) {
            const int kc = k8 * 8 + (lane & 3);
            uint32_t a[2][4];
            #pragma unroll
            for (int mi = 0; mi < 2; mi++) {
                int r = wm * 32 + mi * 16 + (lane >> 2);
                if (MODE == 0) {
                    a[mi][0] = f2tf32(As[buf][r][kc]);
                    a[mi][1] = f2tf32(As[buf][r + 8][kc]);
                    a[mi][2] = f2tf32(As[buf][r][kc + 4]);
                    a[mi][3] = f2tf32(As[buf][r + 8][kc + 4]);
                } else {
                    a[mi][0] = __float_as_uint(As[buf][r][kc]);
                    a[mi][1] = __float_as_uint(As[buf][r + 8][kc]);
                    a[mi][2] = __float_as_uint(As[buf][r][kc + 4]);
                    a[mi][3] = __float_as_uint(As[buf][r + 8][kc + 4]);
                }
            }
            uint32_t b[8][2];
            #pragma unroll
            for (int ni = 0; ni < 8; ni++) {
                int n = wn * 64 + ni * 8 + (lane >> 2);
                b[ni][0] = __float_as_uint(Bs[buf][n][kc]);
                b[ni][1] = __float_as_uint(Bs[buf][n][kc + 4]);
            }
            #pragma unroll
            for (int mi = 0; mi < 2; mi++)
                #pragma unroll
                for (int ni = 0; ni < 8; ni++)
                    mma_tf32(acc[mi][ni], a[mi], b[ni]);
        }
        __syncthreads();
        if (s + 2 < S) issue(s + 2);
    }

    // epilogue
    float sc[16], sq[16];
    if (MODE == 1) {
        #pragma unroll
        for (int i = 0; i < 16; i++) { sc[i] = 0.f; sq[i] = 0.f; }
    }
    #pragma unroll
    for (int mi = 0; mi < 2; mi++) {
        const int r0 = m0 + wm * 32 + mi * 16 + (lane >> 2);
        #pragma unroll
        for (int ni = 0; ni < 8; ni++) {
            const int col = n0 + wn * 64 + ni * 8 + (lane & 3) * 2;
            const float bx = __ldg(&bias[col]);
            const float by = __ldg(&bias[col + 1]);
            float2 v;
            if (r0 < M) {
                v.x = acc[mi][ni][0] + bx;
                v.y = acc[mi][ni][1] + by;
                if (MODE == 0) {
                    v.x = __uint_as_float(f2tf32(fmaxf(v.x, 0.f)));
                    v.y = __uint_as_float(f2tf32(fmaxf(v.y, 0.f)));
                } else {
                    sc[ni * 2]     += v.x;  sq[ni * 2]     = fmaf(v.x, v.x, sq[ni * 2]);
                    sc[ni * 2 + 1] += v.y;  sq[ni * 2 + 1] = fmaf(v.y, v.y, sq[ni * 2 + 1]);
                }
                *(float2*)&C[(size_t)r0 * N + col] = v;
            }
            if (r0 + 8 < M) {
                v.x = acc[mi][ni][2] + bx;
                v.y = acc[mi][ni][3] + by;
                if (MODE == 0) {
                    v.x = __uint_as_float(f2tf32(fmaxf(v.x, 0.f)));
                    v.y = __uint_as_float(f2tf32(fmaxf(v.y, 0.f)));
                } else {
                    sc[ni * 2]     += v.x;  sq[ni * 2]     = fmaf(v.x, v.x, sq[ni * 2]);
                    sc[ni * 2 + 1] += v.y;  sq[ni * 2 + 1] = fmaf(v.y, v.y, sq[ni * 2 + 1]);
                }
                *(float2*)&C[(size_t)(r0 + 8) * N + col] = v;
            }
        }
    }
    if (MODE == 1) {
        // reduce over the 8 row-groups (lane>>2) -> lanes 0..3 hold warp column sums
        #pragma unroll
        for (int i = 0; i < 16; i++) {
            #pragma unroll
            for (int off = 16; off >= 4; off >>= 1) {
                sc[i] += __shfl_down_sync(0xFFFFFFFFu, sc[i], off);
                sq[i] += __shfl_down_sync(0xFFFFFFFFu, sq[i], off);
            }
        }
        if (lane < 4) {
            #pragma unroll
            for (int i = 0; i < 16; i++) {
                int col = n0 + wn * 64 + (i >> 1) * 8 + lane * 2 + (i & 1);
                atomicAdd(&g_sum[col], sc[i]);
                atomicAdd(&g_sumsq[col], sq[i]);
            }
        }
    }
}

// ================= BN finalize =================
__global__ void bn_finalize_kernel(const float* __restrict__ gamma,
                                   const float* __restrict__ beta) {
    int c = threadIdx.x;
    float inv_n = 1.0f / (float)N_NODES;
    float mean = g_sum[c] * inv_n;
    float var  = g_sumsq[c] * inv_n - mean * mean;
    float sc   = gamma[c] * rsqrtf(var + BN_EPS);
    g_scale[c] = sc;
    g_shift[c] = beta[c] - mean * sc;
}

// ================= fused BN-apply + ReLU + classifier =================
__global__ __launch_bounds__(256)
void cls_kernel(const float* __restrict__ Wc, const float* __restrict__ bc,
                float* __restrict__ out) {
    __shared__ float s_scale[HIDDEN], s_shift[HIDDEN], s_w0[HIDDEN], s_w1[HIDDEN];
    int tid = threadIdx.x;
    for (int c = tid; c < HIDDEN; c += 256) {
        s_scale[c] = g_scale[c];
        s_shift[c] = g_shift[c];
        s_w0[c] = Wc[c * 2 + 0];
        s_w1[c] = Wc[c * 2 + 1];
    }
    __syncthreads();

    int warp = tid >> 5, lane = tid & 31;
    int row = blockIdx.x * 8 + warp;
    const float4* h = (const float4*)&g_h2[(long long)row * HIDDEN];
    float a0 = 0.f, a1 = 0.f;
    #pragma unroll
    for (int it = 0; it < 4; it++) {
        int c4 = it * 32 + lane;
        float4 v = h[c4];
        int c = c4 * 4;
        float t;
        t = fmaxf(fmaf(v.x, s_scale[c + 0], s_shift[c + 0]), 0.f);
        a0 = fmaf(t, s_w0[c + 0], a0); a1 = fmaf(t, s_w1[c + 0], a1);
        t = fmaxf(fmaf(v.y, s_scale[c + 1], s_shift[c + 1]), 0.f);
        a0 = fmaf(t, s_w0[c + 1], a0); a1 = fmaf(t, s_w1[c + 1], a1);
        t = fmaxf(fmaf(v.z, s_scale[c + 2], s_shift[c + 2]), 0.f);
        a0 = fmaf(t, s_w0[c + 2], a0); a1 = fmaf(t, s_w1[c + 2], a1);
        t = fmaxf(fmaf(v.w, s_scale[c + 3], s_shift[c + 3]), 0.f);
        a0 = fmaf(t, s_w0[c + 3], a0); a1 = fmaf(t, s_w1[c + 3], a1);
    }
    #pragma unroll
    for (int o = 16; o > 0; o >>= 1) {
        a0 += __shfl_down_sync(0xFFFFFFFFu, a0, o);
        a1 += __shfl_down_sync(0xFFFFFFFFu, a1, o);
    }
    if (lane == 0) {
        out[row * 2 + 0] = a0 + bc[0];
        out[row * 2 + 1] = a1 + bc[1];
    }
}

// ================= launch =================
extern "C" void kernel_launch(void* const* d_in, const int* in_sizes, int n_in,
                              void* d_out, int out_size) {
    const float* x     = (const float*)d_in[0];
    const void*  ei    = d_in[1];
    const float* W1    = (const float*)d_in[2];
    const float* b1    = (const float*)d_in[3];
    const float* W2    = (const float*)d_in[4];
    const float* b2    = (const float*)d_in[5];
    const float* gamma = (const float*)d_in[6];
    const float* beta  = (const float*)d_in[7];
    const float* Wc    = (const float*)d_in[8];
    const float* bc    = (const float*)d_in[9];
    float*       out   = (float*)d_out;

    // 0) detect edge_index dtype
    detect_kernel<<<1, 1>>>((const long long*)ei);

    // 1) agg = x ; zero BN accumulators
    init_kernel<<<(N_NODES * NUM_FEAT / 4) / 256, 256>>>(x);

    // 2) agg[dst] += x[src]   (vector red)
    agg_kernel<<<(N_EDGES * 16) / 256, 256>>>(x, ei);

    // 2b) weight transposes (tf32-rounded)
    tr_kernel<NUM_FEAT><<<dim3(HIDDEN / 32, NUM_FEAT / 32), dim3(32, 32)>>>(W1);
    tr_kernel<HIDDEN>  <<<dim3(HIDDEN / 32, HIDDEN / 32),   dim3(32, 32)>>>(W2);

    // 3) h1 = tf32round(relu(agg @ W1 + b1))
    dim3 gg((N_NODES + 127) / 128, HIDDEN / 128);
    gemm_mma_kernel<0><<<gg, 256>>>(b1);

    // 4) h2 = h1 @ W2 + b2  (+ fused BN column sums)
    gemm_mma_kernel<1><<<gg, 256>>>(b2);

    // 5) BN finalize
    bn_finalize_kernel<<<1, HIDDEN>>>(gamma, beta);

    // 6) out = relu(BN(h2)) @ Wc + bc
    cls_kernel<<<N_NODES / 8, 256>>>(Wc, bc, out);
}

// round 7
// speedup vs baseline: 3.0769x; 1.3351x over previous
#include <cuda_runtime.h>
#include <cuda_bf16.h>
#include <cstdint>

#define N_NODES   50000
#define NUM_FEAT  64
#define HIDDEN    512
#define N_EDGES   800000
#define BN_EPS    1e-5f

// ================= helpers =================
__device__ __forceinline__ uint32_t smem_u32(const void* p) {
    uint32_t a;
    asm("{ .reg .u64 t; cvta.to.shared.u64 t, %1; cvt.u32.u64 %0, t; }" : "=r"(a) : "l"(p));
    return a;
}
__device__ __forceinline__ uint32_t f2tf32(float x) {
    uint32_t u;
    asm("cvt.rna.tf32.f32 %0, %1;" : "=r"(u) : "f"(x));
    return u;
}
__device__ __forceinline__ void mma_tf32(float* d, const uint32_t* a, const uint32_t* b) {
    asm volatile("mma.sync.aligned.m16n8k8.row.col.f32.tf32.tf32.f32 "
        "{%0,%1,%2,%3}, {%4,%5,%6,%7}, {%8,%9}, {%0,%1,%2,%3};"
        : "+f"(d[0]), "+f"(d[1]), "+f"(d[2]), "+f"(d[3])
        : "r"(a[0]), "r"(a[1]), "r"(a[2]), "r"(a[3]), "r"(b[0]), "r"(b[1]));
}
__device__ __forceinline__ void cp_async16(uint32_t dst, const void* src, int src_bytes) {
    asm volatile("cp.async.cg.shared.global [%0], [%1], 16, %2;"
                 :: "r"(dst), "l"(src), "r"(src_bytes) : "memory");
}
#define CP_COMMIT() asm volatile("cp.async.commit_group;" ::: "memory")

// ================= scratch (static device globals) =================
__device__ float g_agg[(size_t)N_NODES * NUM_FEAT];     // 12.8 MB
__device__ float g_h1 [(size_t)N_NODES * HIDDEN];       // 102.4 MB (tf32-rounded)
__device__ float g_h2 [(size_t)N_NODES * HIDDEN];       // 102.4 MB
__device__ float g_w1t[(size_t)HIDDEN * NUM_FEAT];      // W1 fragment-ordered
__device__ float g_w2t[(size_t)HIDDEN * HIDDEN];        // W2 fragment-ordered
__device__ float g_sum  [HIDDEN];
__device__ float g_sumsq[HIDDEN];
__device__ float g_scale[HIDDEN];
__device__ float g_shift[HIDDEN];
__device__ int   g_idx64;

// ================= dtype detect (int64 vs int32 edge_index) =================
__global__ void detect_kernel(const long long* __restrict__ ei) {
    int is64 = 1;
    for (int i = 0; i < 64; i++) {
        long long v = ei[i];
        if (v < 0 || v >= N_NODES) { is64 = 0; break; }
    }
    g_idx64 = is64;
}

// ================= init: agg = x, zero BN accumulators =================
__global__ void init_kernel(const float* __restrict__ x) {
    int i = blockIdx.x * blockDim.x + threadIdx.x;
    ((float4*)g_agg)[i] = ((const float4*)x)[i];
    if (i < HIDDEN) { g_sum[i] = 0.f; g_sumsq[i] = 0.f; }
}

// ================= edge aggregation: agg[dst] += x[src] =================
__global__ void agg_kernel(const float* __restrict__ x, const void* __restrict__ ei_raw) {
    int g = blockIdx.x * blockDim.x + threadIdx.x;
    int e = g >> 4;
    int c = (g & 15) << 2;
    if (e >= N_EDGES) return;
    int src, dst;
    if (g_idx64) {
        const long long* ei = (const long long*)ei_raw;
        src = (int)ei[e];
        dst = (int)ei[N_EDGES + e];
    } else {
        const int* ei = (const int*)ei_raw;
        src = ei[e];
        dst = ei[N_EDGES + e];
    }
    if ((unsigned)src >= N_NODES || (unsigned)dst >= N_NODES) return;
    float4 v = *(const float4*)&x[src * NUM_FEAT + c];
    float* d = &g_agg[dst * NUM_FEAT + c];
    asm volatile("red.global.add.v4.f32 [%0], {%1, %2, %3, %4};"
                 :: "l"(d), "f"(v.x), "f"(v.y), "f"(v.z), "f"(v.w) : "memory");
}

// ================= weight -> fragment-ordered layout (tf32-rounded) =================
// Layout per n-block(128 cols) per k-stage(32 K):
//   float4 index i4 = ((k8*2 + wn)*4 + nip)*32 + lane        (i4 in [0,1024))
//   components: (n0,kc), (n0,kc+4), (n0+8,kc), (n0+8,kc+4)
//   n0 = nb*128 + wn*64 + nip*16 + (lane>>2);  kc = stage*32 + k8*8 + (lane&3)
template<int KR>
__global__ void tr_kernel(const float* __restrict__ W) {
    constexpr int S = KR / 32;
    float4* dst = (float4*)((KR == NUM_FEAT) ? g_w1t : g_w2t);
    int g = blockIdx.x * 256 + threadIdx.x;      // total = 512*KR/4
    int nb = g / (S * 1024);
    int rem = g % (S * 1024);
    int stage = rem >> 10;
    int i4 = rem & 1023;
    int lane = i4 & 31, nip = (i4 >> 5) & 3, wn = (i4 >> 7) & 1, k8 = i4 >> 8;
    int n0 = nb * 128 + wn * 64 + nip * 16 + (lane >> 2);
    int kc = stage * 32 + k8 * 8 + (lane & 3);
    float4 v;
    v.x = __uint_as_float(f2tf32(W[(size_t)kc * HIDDEN + n0]));
    v.y = __uint_as_float(f2tf32(W[(size_t)(kc + 4) * HIDDEN + n0]));
    v.z = __uint_as_float(f2tf32(W[(size_t)kc * HIDDEN + n0 + 8]));
    v.w = __uint_as_float(f2tf32(W[(size_t)(kc + 4) * HIDDEN + n0 + 8]));
    dst[g] = v;
}

// ================= tf32 mma.sync GEMM =================
// MODE 0: g_h1 = tf32round(relu(g_agg @ W1 + b1))   [A cvt at fragment load]
// MODE 1: g_h2 = g_h1 @ W2 + b2  + fused BN column stats
// Block 128x128, BK=32, 4 warps (2Mx2N) of 64x64, 3-stage cp.async, 1 sync/stage.
#define ASTRIDE 36
#define ABUF (128 * ASTRIDE)
#define BBUF 4096
#define SMEM_GEMM_BYTES ((3 * ABUF + 3 * BBUF) * 4)   // 104448

template<int MODE>
__global__ __launch_bounds__(128)
void gemm_mma_kernel(const float* __restrict__ bias) {
    constexpr int M = N_NODES;
    constexpr int N = HIDDEN;
    constexpr int K = (MODE == 0) ? NUM_FEAT : HIDDEN;
    constexpr int S = K / 32;
    const float* __restrict__ A  = (MODE == 0) ? g_agg : g_h1;
    const float* __restrict__ WT = (MODE == 0) ? g_w1t : g_w2t;
    float* __restrict__ C        = (MODE == 0) ? g_h1  : g_h2;

    extern __shared__ float sm[];
    float* Asm = sm;                 // 3 x [128][36]
    float* Bsm = sm + 3 * ABUF;      // 3 x [4096]

    const int tid  = threadIdx.x;
    const int lane = tid & 31;
    const int wid  = tid >> 5;
    const int wm   = wid >> 1;       // 0..1
    const int wn   = wid & 1;        // 0..1
    const int m0   = blockIdx.x * 128;
    const int nb   = blockIdx.y;

    auto issue = [&](int s) {
        const int buf = s % 3;
        float* Ab = Asm + buf * ABUF;
        float* Bb = Bsm + buf * BBUF;
        const int k0 = s * 32;
        #pragma unroll
        for (int i = 0; i < 8; i++) {
            int idx = tid + i * 128;             // 0..1023
            int r = idx >> 3, q = (idx & 7) << 2;
            int row = m0 + r;
            bool v = row < M;
            long long rc = v ? row : (M - 1);
            cp_async16(smem_u32(&Ab[r * ASTRIDE + q]), &A[rc * (long long)K + k0 + q], v ? 16 : 0);
        }
        const float* src = WT + ((size_t)nb * S + s) * BBUF;
        #pragma unroll
        for (int i = 0; i < 8; i++) {
            int idx = tid + i * 128;
            cp_async16(smem_u32(&Bb[idx * 4]), src + idx * 4, 16);
        }
        CP_COMMIT();
    };

    float acc[4][8][4];
    #pragma unroll
    for (int mi = 0; mi < 4; mi++)
        #pragma unroll
        for (int ni = 0; ni < 8; ni++)
            #pragma unroll
            for (int j = 0; j < 4; j++) acc[mi][ni][j] = 0.f;

    issue(0);
    if (S > 1) issue(1);

    #pragma unroll 1
    for (int s = 0; s < S; s++) {
        if (s + 1 < S) asm volatile("cp.async.wait_group 1;" ::: "memory");
        else           asm volatile("cp.async.wait_group 0;" ::: "memory");
        __syncthreads();
        const int buf = s % 3;
        const float* Ab = Asm + buf * ABUF;
        const float* Bb = Bsm + buf * BBUF;

        #pragma unroll
        for (int k8 = 0; k8 < 4; k8++) {
            const int kc = k8 * 8 + (lane & 3);
            uint32_t a[4][4];
            #pragma unroll
            for (int mi = 0; mi < 4; mi++) {
                int r = wm * 64 + mi * 16 + (lane >> 2);
                if (MODE == 0) {
                    a[mi][0] = f2tf32(Ab[r * ASTRIDE + kc]);
                    a[mi][1] = f2tf32(Ab[(r + 8) * ASTRIDE + kc]);
                    a[mi][2] = f2tf32(Ab[r * ASTRIDE + kc + 4]);
                    a[mi][3] = f2tf32(Ab[(r + 8) * ASTRIDE + kc + 4]);
                } else {
                    a[mi][0] = __float_as_uint(Ab[r * ASTRIDE + kc]);
                    a[mi][1] = __float_as_uint(Ab[(r + 8) * ASTRIDE + kc]);
                    a[mi][2] = __float_as_uint(Ab[r * ASTRIDE + kc + 4]);
                    a[mi][3] = __float_as_uint(Ab[(r + 8) * ASTRIDE + kc + 4]);
                }
            }
            uint32_t b[8][2];
            #pragma unroll
            for (int nip = 0; nip < 4; nip++) {
                float4 v = *(const float4*)&Bb[(((k8 * 2 + wn) * 4 + nip) * 32 + lane) * 4];
                b[nip * 2][0]     = __float_as_uint(v.x);
                b[nip * 2][1]     = __float_as_uint(v.y);
                b[nip * 2 + 1][0] = __float_as_uint(v.z);
                b[nip * 2 + 1][1] = __float_as_uint(v.w);
            }
            #pragma unroll
            for (int mi = 0; mi < 4; mi++)
                #pragma unroll
                for (int ni = 0; ni < 8; ni++)
                    mma_tf32(acc[mi][ni], a[mi], b[ni]);
        }
        if (s + 2 < S) issue(s + 2);
    }

    // epilogue
    const int n0 = nb * 128;
    float scv[16], sqv[16];
    if (MODE == 1) {
        #pragma unroll
        for (int i = 0; i < 16; i++) { scv[i] = 0.f; sqv[i] = 0.f; }
    }
    #pragma unroll
    for (int mi = 0; mi < 4; mi++) {
        const int r0 = m0 + wm * 64 + mi * 16 + (lane >> 2);
        #pragma unroll
        for (int ni = 0; ni < 8; ni++) {
            const int col = n0 + wn * 64 + ni * 8 + (lane & 3) * 2;
            const float bx = __ldg(&bias[col]);
            const float by = __ldg(&bias[col + 1]);
            float2 v;
            if (r0 < M) {
                v.x = acc[mi][ni][0] + bx;
                v.y = acc[mi][ni][1] + by;
                if (MODE == 0) {
                    v.x = __uint_as_float(f2tf32(fmaxf(v.x, 0.f)));
                    v.y = __uint_as_float(f2tf32(fmaxf(v.y, 0.f)));
                } else {
                    scv[ni * 2]     += v.x;  sqv[ni * 2]     = fmaf(v.x, v.x, sqv[ni * 2]);
                    scv[ni * 2 + 1] += v.y;  sqv[ni * 2 + 1] = fmaf(v.y, v.y, sqv[ni * 2 + 1]);
                }
                *(float2*)&C[(size_t)r0 * N + col] = v;
            }
            if (r0 + 8 < M) {
                v.x = acc[mi][ni][2] + bx;
                v.y = acc[mi][ni][3] + by;
                if (MODE == 0) {
                    v.x = __uint_as_float(f2tf32(fmaxf(v.x, 0.f)));
                    v.y = __uint_as_float(f2tf32(fmaxf(v.y, 0.f)));
                } else {
                    scv[ni * 2]     += v.x;  sqv[ni * 2]     = fmaf(v.x, v.x, sqv[ni * 2]);
                    scv[ni * 2 + 1] += v.y;  sqv[ni * 2 + 1] = fmaf(v.y, v.y, sqv[ni * 2 + 1]);
                }
                *(float2*)&C[(size_t)(r0 + 8) * N + col] = v;
            }
        }
    }
    if (MODE == 1) {
        #pragma unroll
        for (int i = 0; i < 16; i++) {
            #pragma unroll
            for (int off = 16; off >= 4; off >>= 1) {
                scv[i] += __shfl_down_sync(0xFFFFFFFFu, scv[i], off);
                sqv[i] += __shfl_down_sync(0xFFFFFFFFu, sqv[i], off);
            }
        }
        if (lane < 4) {
            #pragma unroll
            for (int i = 0; i < 16; i++) {
                int col = n0 + wn * 64 + (i >> 1) * 8 + lane * 2 + (i & 1);
                atomicAdd(&g_sum[col], scv[i]);
                atomicAdd(&g_sumsq[col], sqv[i]);
            }
        }
    }
}

// ================= BN finalize =================
__global__ void bn_finalize_kernel(const float* __restrict__ gamma,
                                   const float* __restrict__ beta) {
    int c = threadIdx.x;
    float inv_n = 1.0f / (float)N_NODES;
    float mean = g_sum[c] * inv_n;
    float var  = g_sumsq[c] * inv_n - mean * mean;
    float sc   = gamma[c] * rsqrtf(var + BN_EPS);
    g_scale[c] = sc;
    g_shift[c] = beta[c] - mean * sc;
}

// ================= fused BN-apply + ReLU + classifier =================
__global__ __launch_bounds__(256)
void cls_kernel(const float* __restrict__ Wc, const float* __restrict__ bc,
                float* __restrict__ out) {
    __shared__ float s_scale[HIDDEN], s_shift[HIDDEN], s_w0[HIDDEN], s_w1[HIDDEN];
    int tid = threadIdx.x;
    for (int c = tid; c < HIDDEN; c += 256) {
        s_scale[c] = g_scale[c];
        s_shift[c] = g_shift[c];
        s_w0[c] = Wc[c * 2 + 0];
        s_w1[c] = Wc[c * 2 + 1];
    }
    __syncthreads();

    int warp = tid >> 5, lane = tid & 31;
    int row = blockIdx.x * 8 + warp;
    const float4* h = (const float4*)&g_h2[(long long)row * HIDDEN];
    float a0 = 0.f, a1 = 0.f;
    #pragma unroll
    for (int it = 0; it < 4; it++) {
        int c4 = it * 32 + lane;
        float4 v = h[c4];
        int c = c4 * 4;
        float t;
        t = fmaxf(fmaf(v.x, s_scale[c + 0], s_shift[c + 0]), 0.f);
        a0 = fmaf(t, s_w0[c + 0], a0); a1 = fmaf(t, s_w1[c + 0], a1);
        t = fmaxf(fmaf(v.y, s_scale[c + 1], s_shift[c + 1]), 0.f);
        a0 = fmaf(t, s_w0[c + 1], a0); a1 = fmaf(t, s_w1[c + 1], a1);
        t = fmaxf(fmaf(v.z, s_scale[c + 2], s_shift[c + 2]), 0.f);
        a0 = fmaf(t, s_w0[c + 2], a0); a1 = fmaf(t, s_w1[c + 2], a1);
        t = fmaxf(fmaf(v.w, s_scale[c + 3], s_shift[c + 3]), 0.f);
        a0 = fmaf(t, s_w0[c + 3], a0); a1 = fmaf(t, s_w1[c + 3], a1);
    }
    #pragma unroll
    for (int o = 16; o > 0; o >>= 1) {
        a0 += __shfl_down_sync(0xFFFFFFFFu, a0, o);
        a1 += __shfl_down_sync(0xFFFFFFFFu, a1, o);
    }
    if (lane == 0) {
        out[row * 2 + 0] = a0 + bc[0];
        out[row * 2 + 1] = a1 + bc[1];
    }
}

// ================= launch =================
extern "C" void kernel_launch(void* const* d_in, const int* in_sizes, int n_in,
                              void* d_out, int out_size) {
    const float* x     = (const float*)d_in[0];
    const void*  ei    = d_in[1];
    const float* W1    = (const float*)d_in[2];
    const float* b1    = (const float*)d_in[3];
    const float* W2    = (const float*)d_in[4];
    const float* b2    = (const float*)d_in[5];
    const float* gamma = (const float*)d_in[6];
    const float* beta  = (const float*)d_in[7];
    const float* Wc    = (const float*)d_in[8];
    const float* bc    = (const float*)d_in[9];
    float*       out   = (float*)d_out;

    cudaFuncSetAttribute(gemm_mma_kernel<0>, cudaFuncAttributeMaxDynamicSharedMemorySize, SMEM_GEMM_BYTES);
    cudaFuncSetAttribute(gemm_mma_kernel<1>, cudaFuncAttributeMaxDynamicSharedMemorySize, SMEM_GEMM_BYTES);

    // 0) detect edge_index dtype
    detect_kernel<<<1, 1>>>((const long long*)ei);

    // 1) agg = x ; zero BN accumulators
    init_kernel<<<(N_NODES * NUM_FEAT / 4) / 256, 256>>>(x);

    // 2) agg[dst] += x[src]   (vector red)
    agg_kernel<<<(N_EDGES * 16) / 256, 256>>>(x, ei);

    // 2b) weights -> fragment-ordered layout (tf32-rounded)
    tr_kernel<NUM_FEAT><<<(512 * NUM_FEAT / 4) / 256, 256>>>(W1);
    tr_kernel<HIDDEN>  <<<(512 * HIDDEN / 4) / 256, 256>>>(W2);

    // 3) h1 = tf32round(relu(agg @ W1 + b1))
    dim3 gg((N_NODES + 127) / 128, HIDDEN / 128);
    gemm_mma_kernel<0><<<gg, 128, SMEM_GEMM_BYTES>>>(b1);

    // 4) h2 = h1 @ W2 + b2  (+ fused BN column sums)
    gemm_mma_kernel<1><<<gg, 128, SMEM_GEMM_BYTES>>>(b2);

    // 5) BN finalize
    bn_finalize_kernel<<<1, HIDDEN>>>(gamma, beta);

    // 6) out = relu(BN(h2)) @ Wc + bc
    cls_kernel<<<N_NODES / 8, 256>>>(Wc, bc, out);
}